// round 9
// baseline (speedup 1.0000x reference)
#include <cuda_runtime.h>
#include <math.h>
#include <stdint.h>

#define KDIM   4096
#define RROWS  24
#define MAXNT  8192

// ---- fused kernel geometry ----
#define MTOK   64                  // tokens per block
#define CKM    64                  // k per chunk per group
#define NCHG   32                  // chunks per group (2048/64)
#define NBUFM  3
#define XROW   68                  // padded floats per smem row
#define XSZ    (MTOK * XROW * 4)   // 17408 B
#define WSZ    (RROWS * XROW * 4)  // 6528 B
#define STGB   (XSZ + WSZ)         // 23936 B
#define GRPB   (NBUFM * STGB)      // 71808 B per group
// float offsets within dynamic smem after staging region
#define OFF_PART (2 * GRPB)                    // sP  [64*24] f32
#define OFF_DOTS (OFF_PART + 64 * 24 * 4)      // sdots[64*24]
#define OFF_H    (OFF_DOTS + 64 * 24 * 4)      // sH  [64*24]
#define OFF_SQB  (OFF_H    + 64 * 24 * 4)      // sSqB[64]
#define OFF_SQ   (OFF_SQB  + 64 * 4)           // sSq [64]
#define SMEMF    (OFF_SQ   + 64 * 4)           // 162,560 B

// -------- scratch (no cudaMalloc allowed) --------
__device__ float g_wN[RROWS * KDIM];   // gamma-folded, tf32-rounded weights

// ---------------- helpers ----------------
__device__ __forceinline__ void cpasync16(void* dst_smem, const void* src) {
    unsigned d = (unsigned)__cvta_generic_to_shared(dst_smem);
    asm volatile("cp.async.cg.shared.global [%0], [%1], 16;" :: "r"(d), "l"(src));
}
__device__ __forceinline__ float ex2f(float x) {
    float r; asm("ex2.approx.f32 %0, %1;" : "=f"(r) : "f"(x)); return r;
}
__device__ __forceinline__ float lg2f(float x) {
    float r; asm("lg2.approx.f32 %0, %1;" : "=f"(r) : "f"(x)); return r;
}
__device__ __forceinline__ uint32_t tf32r(float f) {
    uint32_t r; asm("cvt.rna.tf32.f32 %0, %1;" : "=r"(r) : "f"(f)); return r;
}
__device__ __forceinline__ void mma8(float* c, uint32_t a0, uint32_t a1,
                                     uint32_t a2, uint32_t a3,
                                     uint32_t b0, uint32_t b1) {
    asm volatile(
        "mma.sync.aligned.m16n8k8.row.col.f32.tf32.tf32.f32 "
        "{%0,%1,%2,%3}, {%4,%5,%6,%7}, {%8,%9}, {%0,%1,%2,%3};"
        : "+f"(c[0]), "+f"(c[1]), "+f"(c[2]), "+f"(c[3])
        : "r"(a0), "r"(a1), "r"(a2), "r"(a3), "r"(b0), "r"(b1));
}

#define LOG2E 1.4426950408889634f
__device__ __forceinline__ float lse4_2(float a, float b, float c, float d) {
    float m = fmaxf(fmaxf(a, b), fmaxf(c, d));
    float s = ex2f(a - m) + ex2f(b - m) + ex2f(c - m) + ex2f(d - m);
    return m + lg2f(s);
}

// ============================================================
// K0: fold gamma into weights, round to tf32 once
// ============================================================
__global__ void prep_kernel(const float* __restrict__ w_res,
                            const float* __restrict__ w_pre,
                            const float* __restrict__ w_post,
                            const float* __restrict__ gamma) {
    int idx = blockIdx.x * blockDim.x + threadIdx.x;
    if (idx >= RROWS * KDIM) return;
    int r = idx >> 12;
    int k = idx & (KDIM - 1);
    float w;
    if (r < 16)      w = w_res [r * KDIM + k];
    else if (r < 20) w = w_pre [(r - 16) * KDIM + k];
    else             w = w_post[(r - 20) * KDIM + k];
    g_wN[idx] = __uint_as_float(tf32r(w * (1.0f + gamma[k])));
}

// ============================================================
// FUSED: dots (mma.sync tf32, K split across 2 warp-groups)
//        -> sinkhorn/softmax/sigmoid heads (in smem)
//        -> mix (re-read x tile, L2-warm) -> out
// 128 blocks x 256 threads, 64 tokens/block.
// ============================================================
__global__ void __launch_bounds__(256, 1)
fused_kernel(const float* __restrict__ x, float* __restrict__ out,
             const float* __restrict__ beta_res,
             const float* __restrict__ beta_pre,
             const float* __restrict__ beta_post,
             const float* __restrict__ alpha_res,
             const float* __restrict__ alpha_pre,
             const float* __restrict__ alpha_post) {
    extern __shared__ __align__(16) char sm[];
    const int tid  = threadIdx.x;
    const int lane = tid & 31;
    const int warp = tid >> 5;            // 0..7
    const int grp  = warp >> 2;           // K-half
    const int mt   = warp & 3;            // m-tile
    const int g    = lane >> 2;           // 0..7
    const int tig  = lane & 3;            // 0..3
    const int tokb = blockIdx.x * MTOK;

    float* sP    = (float*)(sm + OFF_PART);
    float* sdots = (float*)(sm + OFF_DOTS);
    float* sH    = (float*)(sm + OFF_H);
    float* sSqB  = (float*)(sm + OFF_SQB);
    float* sSq   = (float*)(sm + OFF_SQ);

    // stage chunk s for BOTH groups, one commit
#define STAGE(s) do {                                                          \
        if ((s) < NCHG) {                                                      \
            _Pragma("unroll")                                                  \
            for (int _G = 0; _G < 2; ++_G) {                                   \
                char* _b = sm + _G * GRPB + ((s) % NBUFM) * STGB;              \
                int _ko = _G * 2048 + (s) * CKM;                               \
                _Pragma("unroll")                                              \
                for (int _j = 0; _j < 4; ++_j) {                               \
                    int _i = tid + 256 * _j;                                   \
                    int _t = _i >> 4, _c = _i & 15;                            \
                    cpasync16(_b + _t * (XROW * 4) + _c * 16,                  \
                              x + (size_t)(tokb + _t) * KDIM + _ko + _c * 4);  \
                }                                                              \
                _Pragma("unroll")                                              \
                for (int _j = 0; _j < 2; ++_j) {                               \
                    int _i = tid + 256 * _j;                                   \
                    if (_i < 384) {                                            \
                        int _t = _i >> 4, _c = _i & 15;                        \
                        cpasync16(_b + XSZ + _t * (XROW * 4) + _c * 16,        \
                                  g_wN + _t * KDIM + _ko + _c * 4);            \
                    }                                                          \
                }                                                              \
            }                                                                  \
        }                                                                      \
        asm volatile("cp.async.commit_group;");                                \
    } while (0)

    float acc[3][4];
#pragma unroll
    for (int nt = 0; nt < 3; ++nt)
#pragma unroll
        for (int i = 0; i < 4; ++i) acc[nt][i] = 0.0f;
    float ssq0 = 0.0f, ssq1 = 0.0f;

    STAGE(0);
    STAGE(1);

    const int rowA0 = (mt * 16 + g) * XROW;
    const int rowA1 = rowA0 + 8 * XROW;

    for (int ch = 0; ch < NCHG; ++ch) {
        STAGE(ch + 2);
        asm volatile("cp.async.wait_group 2;" ::: "memory");
        __syncthreads();

        const float* xb = (const float*)(sm + grp * GRPB + (ch % NBUFM) * STGB);
        const float* wb = xb + MTOK * XROW;

#pragma unroll
        for (int kt = 0; kt < 8; ++kt) {
            const int k0 = kt * 8 + tig;
            float a0f = xb[rowA0 + k0];
            float a1f = xb[rowA1 + k0];
            float a2f = xb[rowA0 + k0 + 4];
            float a3f = xb[rowA1 + k0 + 4];
            ssq0 = fmaf(a0f, a0f, fmaf(a2f, a2f, ssq0));
            ssq1 = fmaf(a1f, a1f, fmaf(a3f, a3f, ssq1));
            uint32_t A0 = tf32r(a0f), A1 = tf32r(a1f);
            uint32_t A2 = tf32r(a2f), A3 = tf32r(a3f);
#pragma unroll
            for (int nt = 0; nt < 3; ++nt) {
                uint32_t B0 = __float_as_uint(wb[(nt * 8 + g) * XROW + k0]);
                uint32_t B1 = __float_as_uint(wb[(nt * 8 + g) * XROW + k0 + 4]);
                mma8(acc[nt], A0, A1, A2, A3, B0, B1);
            }
        }
        __syncthreads();
    }

    // ---- combine the two K-half partials ----
    const int t0l = mt * 16 + g;           // local token ids
    const int t1l = t0l + 8;

    ssq0 += __shfl_down_sync(0xffffffffu, ssq0, 2, 4);
    ssq0 += __shfl_down_sync(0xffffffffu, ssq0, 1, 4);
    ssq1 += __shfl_down_sync(0xffffffffu, ssq1, 2, 4);
    ssq1 += __shfl_down_sync(0xffffffffu, ssq1, 1, 4);

    if (grp == 1) {                         // group B -> smem partials
#pragma unroll
        for (int nt = 0; nt < 3; ++nt) {
            int r = nt * 8 + 2 * tig;
            *(float2*)(sP + t0l * 24 + r) = make_float2(acc[nt][0], acc[nt][1]);
            *(float2*)(sP + t1l * 24 + r) = make_float2(acc[nt][2], acc[nt][3]);
        }
        if (tig == 0) { sSqB[t0l] = ssq0; sSqB[t1l] = ssq1; }
    }
    __syncthreads();
    if (grp == 0) {                         // group A adds & finalizes
#pragma unroll
        for (int nt = 0; nt < 3; ++nt) {
            int r = nt * 8 + 2 * tig;
            float2 p0 = *(const float2*)(sP + t0l * 24 + r);
            float2 p1 = *(const float2*)(sP + t1l * 24 + r);
            *(float2*)(sdots + t0l * 24 + r) =
                make_float2(acc[nt][0] + p0.x, acc[nt][1] + p0.y);
            *(float2*)(sdots + t1l * 24 + r) =
                make_float2(acc[nt][2] + p1.x, acc[nt][3] + p1.y);
        }
        if (tig == 0) {
            sSq[t0l] = ssq0 + sSqB[t0l];
            sSq[t1l] = ssq1 + sSqB[t1l];
        }
    }
    __syncthreads();

    // ---- heads: one thread per token (threads 0..63) ----
    if (tid < MTOK) {
        const int t = tid;
        float rstd = 64.0f / fmaxf(sqrtf(sSq[t]), 1e-12f);
        const float* dp = sdots + t * 24;
        float ar = alpha_res[0]  * rstd;
        float ap = alpha_pre[0]  * rstd;
        float ao = alpha_post[0] * rstd;

        float Z[16];
#pragma unroll
        for (int e = 0; e < 16; ++e)
            Z[e] = (beta_res[e] + ar * dp[e]) * (20.0f * LOG2E);

        float u[4] = {0.f, 0.f, 0.f, 0.f};
        float v[4] = {0.f, 0.f, 0.f, 0.f};
#pragma unroll 1
        for (int itn = 0; itn < 10; ++itn) {
#pragma unroll
            for (int i = 0; i < 4; ++i)
                u[i] = -lse4_2(Z[i*4+0] + v[0], Z[i*4+1] + v[1],
                               Z[i*4+2] + v[2], Z[i*4+3] + v[3]);
#pragma unroll
            for (int j = 0; j < 4; ++j)
                v[j] = -lse4_2(Z[0*4+j] + u[0], Z[1*4+j] + u[1],
                               Z[2*4+j] + u[2], Z[3*4+j] + u[3]);
        }

        float* hp = sH + t * 24;
#pragma unroll
        for (int i = 0; i < 4; ++i)
#pragma unroll
            for (int j = 0; j < 4; ++j)
                hp[i*4+j] = ex2f(Z[i*4+j] + u[i] + v[j]);

        float p[4];
#pragma unroll
        for (int s = 0; s < 4; ++s)
            p[s] = (beta_pre[s] + ap * dp[16 + s]) * LOG2E;
        float m = fmaxf(fmaxf(p[0], p[1]), fmaxf(p[2], p[3]));
        float e0 = ex2f(p[0]-m), e1 = ex2f(p[1]-m);
        float e2 = ex2f(p[2]-m), e3 = ex2f(p[3]-m);
        float inv = 1.0f / (e0 + e1 + e2 + e3);
        hp[16] = e0*inv; hp[17] = e1*inv; hp[18] = e2*inv; hp[19] = e3*inv;

#pragma unroll
        for (int s = 0; s < 4; ++s) {
            float q = beta_post[s] + ao * dp[20 + s];
            hp[20 + s] = 2.0f / (1.0f + ex2f(-q * LOG2E));
        }
    }
    __syncthreads();

    // ---- mix: re-read x tile (L2-warm), write out ----
    const int col = tid * 4;               // 256 thr x 4 = 1024 = D
#pragma unroll 2
    for (int t = 0; t < MTOK; ++t) {
        const float* hp = sH + t * 24;
        const float* xr = x   + (size_t)(tokb + t) * KDIM;
        float*       yr = out + (size_t)(tokb + t) * KDIM;

        float4 xj[4];
#pragma unroll
        for (int j = 0; j < 4; ++j)
            xj[j] = *(const float4*)(xr + j * 1024 + col);

        float hpre0 = hp[16], hpre1 = hp[17], hpre2 = hp[18], hpre3 = hp[19];
        float4 bin;
        bin.x = hpre0*xj[0].x + hpre1*xj[1].x + hpre2*xj[2].x + hpre3*xj[3].x;
        bin.y = hpre0*xj[0].y + hpre1*xj[1].y + hpre2*xj[2].y + hpre3*xj[3].y;
        bin.z = hpre0*xj[0].z + hpre1*xj[1].z + hpre2*xj[2].z + hpre3*xj[3].z;
        bin.w = hpre0*xj[0].w + hpre1*xj[1].w + hpre2*xj[2].w + hpre3*xj[3].w;

#pragma unroll
        for (int i = 0; i < 4; ++i) {
            float hq = hp[20 + i];
            float4 o;
            o.x = hq*bin.x; o.y = hq*bin.y; o.z = hq*bin.z; o.w = hq*bin.w;
#pragma unroll
            for (int j = 0; j < 4; ++j) {
                float h = hp[i*4 + j];
                o.x += h * xj[j].x; o.y += h * xj[j].y;
                o.z += h * xj[j].z; o.w += h * xj[j].w;
            }
            __stcs((float4*)(yr + i * 1024 + col), o);
        }
    }
#undef STAGE
}

// ============================================================
// launch
// ============================================================
extern "C" void kernel_launch(void* const* d_in, const int* in_sizes, int n_in,
                              void* d_out, int out_size) {
    const float* residuals  = (const float*)d_in[0];
    const float* gamma      = (const float*)d_in[1];
    const float* w_res      = (const float*)d_in[2];
    const float* w_pre      = (const float*)d_in[3];
    const float* w_post     = (const float*)d_in[4];
    const float* beta_res   = (const float*)d_in[5];
    const float* beta_pre   = (const float*)d_in[6];
    const float* beta_post  = (const float*)d_in[7];
    const float* alpha_res  = (const float*)d_in[8];
    const float* alpha_pre  = (const float*)d_in[9];
    const float* alpha_post = (const float*)d_in[10];

    const int nt = in_sizes[0] / KDIM;   // B*T tokens (8192)

    static bool attr_set = false;
    if (!attr_set) {
        cudaFuncSetAttribute(fused_kernel,
                             cudaFuncAttributeMaxDynamicSharedMemorySize,
                             SMEMF);
        attr_set = true;
    }

    prep_kernel<<<(RROWS * KDIM + 255) / 256, 256>>>(w_res, w_pre, w_post, gamma);
    fused_kernel<<<nt / MTOK, 256, SMEMF>>>(residuals, (float*)d_out,
                                            beta_res, beta_pre, beta_post,
                                            alpha_res, alpha_pre, alpha_post);
}

// round 10
// speedup vs baseline: 1.1697x; 1.1697x over previous
#include <cuda_runtime.h>
#include <math.h>
#include <stdint.h>

#define KDIM   4096
#define RROWS  24
#define MAXNT  8192

// ---- dots_mma geometry ----
#define MTOK   32                 // tokens per block
#define CKM    64                 // k per chunk
#define NCHM   (KDIM / CKM)       // 64 chunks
#define NBUFM  3
#define XROW   68                 // padded floats per smem row
#define XSZ    (MTOK * XROW * 4)  // 8704 B
#define WSZ    (RROWS * XROW * 4) // 6528 B
#define STGB   (XSZ + WSZ)        // 15232 B
#define OFF_P  (NBUFM * STGB)             // partials [32*24] f32
#define OFF_Q  (OFF_P + MTOK * RROWS * 4) // ssq partials [32]
#define SMEMD  (OFF_Q + MTOK * 4)         // 48,896 B

// -------- scratch (no cudaMalloc allowed) --------
__device__ float g_wN  [RROWS * KDIM];   // gamma-folded, tf32-rounded weights
__device__ float g_dots[MAXNT * RROWS];
__device__ float g_ssq [MAXNT];
__device__ float g_H   [MAXNT * RROWS];

// ---------------- helpers ----------------
__device__ __forceinline__ void cpasync16(void* dst_smem, const void* src) {
    unsigned d = (unsigned)__cvta_generic_to_shared(dst_smem);
    asm volatile("cp.async.cg.shared.global [%0], [%1], 16;" :: "r"(d), "l"(src));
}
__device__ __forceinline__ float ex2f(float x) {
    float r; asm("ex2.approx.f32 %0, %1;" : "=f"(r) : "f"(x)); return r;
}
__device__ __forceinline__ float lg2f(float x) {
    float r; asm("lg2.approx.f32 %0, %1;" : "=f"(r) : "f"(x)); return r;
}
__device__ __forceinline__ uint32_t tf32r(float f) {
    uint32_t r; asm("cvt.rna.tf32.f32 %0, %1;" : "=r"(r) : "f"(f)); return r;
}
__device__ __forceinline__ void mma8(float* c, uint32_t a0, uint32_t a1,
                                     uint32_t a2, uint32_t a3,
                                     uint32_t b0, uint32_t b1) {
    asm volatile(
        "mma.sync.aligned.m16n8k8.row.col.f32.tf32.tf32.f32 "
        "{%0,%1,%2,%3}, {%4,%5,%6,%7}, {%8,%9}, {%0,%1,%2,%3};"
        : "+f"(c[0]), "+f"(c[1]), "+f"(c[2]), "+f"(c[3])
        : "r"(a0), "r"(a1), "r"(a2), "r"(a3), "r"(b0), "r"(b1));
}

// ============================================================
// K0: fold gamma into weights, round to tf32 once
// ============================================================
__global__ void prep_kernel(const float* __restrict__ w_res,
                            const float* __restrict__ w_pre,
                            const float* __restrict__ w_post,
                            const float* __restrict__ gamma) {
    int idx = blockIdx.x * blockDim.x + threadIdx.x;
    if (idx >= RROWS * KDIM) return;
    int r = idx >> 12;
    int k = idx & (KDIM - 1);
    float w;
    if (r < 16)      w = w_res [r * KDIM + k];
    else if (r < 20) w = w_pre [(r - 16) * KDIM + k];
    else             w = w_post[(r - 20) * KDIM + k];
    g_wN[idx] = __uint_as_float(tf32r(w * (1.0f + gamma[k])));
}

// ============================================================
// K1: dots via mma.sync m16n8k8 tf32 -- occupancy-fixed.
// Block = 32 tokens, 128 threads (4 warps), grid = 256 blocks.
// Warp = (m-tile = warp&1) x (K-half of each 64k chunk = warp>>1).
// 4 blocks/SM resident (48.9 KB smem) -> 16 warps/SM.
// K-half partials combined once through smem at the end.
// ============================================================
__global__ void __launch_bounds__(128, 4)
dots_mma(const float* __restrict__ x) {
    extern __shared__ __align__(16) char sm[];
    const int tid  = threadIdx.x;
    const int lane = tid & 31;
    const int warp = tid >> 5;            // 0..3
    const int mt   = warp & 1;            // m-tile
    const int grp  = warp >> 1;           // K-half of chunk
    const int g    = lane >> 2;           // 0..7
    const int tig  = lane & 3;            // 0..3
    const int tokb = blockIdx.x * MTOK;

    float* sP = (float*)(sm + OFF_P);
    float* sQ = (float*)(sm + OFF_Q);

#define STAGE(s) do {                                                          \
        if ((s) < NCHM) {                                                      \
            char* _b = sm + ((s) % NBUFM) * STGB;                              \
            const float* _xs = x + (size_t)tokb * KDIM + (s) * CKM;            \
            _Pragma("unroll")                                                  \
            for (int _j = 0; _j < 4; ++_j) {                                   \
                int _i = tid + 128 * _j;                                       \
                int _t = _i >> 4, _c = _i & 15;                                \
                cpasync16(_b + _t * (XROW * 4) + _c * 16,                      \
                          _xs + (size_t)_t * KDIM + _c * 4);                   \
            }                                                                  \
            _Pragma("unroll")                                                  \
            for (int _j = 0; _j < 3; ++_j) {                                   \
                int _i = tid + 128 * _j;                                       \
                int _t = _i >> 4, _c = _i & 15;                                \
                cpasync16(_b + XSZ + _t * (XROW * 4) + _c * 16,                \
                          g_wN + _t * KDIM + (s) * CKM + _c * 4);              \
            }                                                                  \
        }                                                                      \
        asm volatile("cp.async.commit_group;");                                \
    } while (0)

    float acc[3][4];
#pragma unroll
    for (int nt = 0; nt < 3; ++nt)
#pragma unroll
        for (int i = 0; i < 4; ++i) acc[nt][i] = 0.0f;
    float ssq0 = 0.0f, ssq1 = 0.0f;

    STAGE(0);
    STAGE(1);

    const int rowA0 = (mt * 16 + g) * XROW;
    const int rowA1 = rowA0 + 8 * XROW;

    for (int ch = 0; ch < NCHM; ++ch) {
        STAGE(ch + 2);
        asm volatile("cp.async.wait_group 2;" ::: "memory");
        __syncthreads();

        const float* xb = (const float*)(sm + (ch % NBUFM) * STGB);
        const float* wb = xb + MTOK * XROW;

#pragma unroll
        for (int kt = 0; kt < 4; ++kt) {
            const int k0 = (grp * 4 + kt) * 8 + tig;
            float a0f = xb[rowA0 + k0];
            float a1f = xb[rowA1 + k0];
            float a2f = xb[rowA0 + k0 + 4];
            float a3f = xb[rowA1 + k0 + 4];
            ssq0 = fmaf(a0f, a0f, fmaf(a2f, a2f, ssq0));
            ssq1 = fmaf(a1f, a1f, fmaf(a3f, a3f, ssq1));
            uint32_t A0 = tf32r(a0f), A1 = tf32r(a1f);
            uint32_t A2 = tf32r(a2f), A3 = tf32r(a3f);
#pragma unroll
            for (int nt = 0; nt < 3; ++nt) {
                uint32_t B0 = __float_as_uint(wb[(nt * 8 + g) * XROW + k0]);
                uint32_t B1 = __float_as_uint(wb[(nt * 8 + g) * XROW + k0 + 4]);
                mma8(acc[nt], A0, A1, A2, A3, B0, B1);
            }
        }
        __syncthreads();
    }

    // ---- quad-reduce ssq ----
    ssq0 += __shfl_down_sync(0xffffffffu, ssq0, 2, 4);
    ssq0 += __shfl_down_sync(0xffffffffu, ssq0, 1, 4);
    ssq1 += __shfl_down_sync(0xffffffffu, ssq1, 2, 4);
    ssq1 += __shfl_down_sync(0xffffffffu, ssq1, 1, 4);

    const int t0l = mt * 16 + g;
    const int t1l = t0l + 8;

    // ---- combine K-half partials through smem ----
    if (grp == 1) {
#pragma unroll
        for (int nt = 0; nt < 3; ++nt) {
            int r = nt * 8 + 2 * tig;
            *(float2*)(sP + t0l * RROWS + r) = make_float2(acc[nt][0], acc[nt][1]);
            *(float2*)(sP + t1l * RROWS + r) = make_float2(acc[nt][2], acc[nt][3]);
        }
        if (tig == 0) { sQ[t0l] = ssq0; sQ[t1l] = ssq1; }
    }
    __syncthreads();
    if (grp == 0) {
        const int t0 = tokb + t0l, t1 = tokb + t1l;
#pragma unroll
        for (int nt = 0; nt < 3; ++nt) {
            int r = nt * 8 + 2 * tig;
            float2 p0 = *(const float2*)(sP + t0l * RROWS + r);
            float2 p1 = *(const float2*)(sP + t1l * RROWS + r);
            *(float2*)(g_dots + (size_t)t0 * RROWS + r) =
                make_float2(acc[nt][0] + p0.x, acc[nt][1] + p0.y);
            *(float2*)(g_dots + (size_t)t1 * RROWS + r) =
                make_float2(acc[nt][2] + p1.x, acc[nt][3] + p1.y);
        }
        if (tig == 0) {
            g_ssq[t0] = ssq0 + sQ[t0l];
            g_ssq[t1] = ssq1 + sQ[t1l];
        }
    }
#undef STAGE
}

// ============================================================
// K2: per-token heads (sinkhorn + softmax + sigmoid), base-2 MUFU
// ============================================================
#define LOG2E 1.4426950408889634f

__device__ __forceinline__ float lse4_2(float a, float b, float c, float d) {
    float m = fmaxf(fmaxf(a, b), fmaxf(c, d));
    float s = ex2f(a - m) + ex2f(b - m) + ex2f(c - m) + ex2f(d - m);
    return m + lg2f(s);
}

__global__ void heads_kernel(const float* __restrict__ beta_res,
                             const float* __restrict__ beta_pre,
                             const float* __restrict__ beta_post,
                             const float* __restrict__ alpha_res,
                             const float* __restrict__ alpha_pre,
                             const float* __restrict__ alpha_post,
                             int nt) {
    int tok = blockIdx.x * blockDim.x + threadIdx.x;
    if (tok >= nt) return;

    float rstd = 64.0f / fmaxf(sqrtf(g_ssq[tok]), 1e-12f);
    const float* dp = g_dots + (size_t)tok * RROWS;
    float ar = alpha_res[0]  * rstd;
    float ap = alpha_pre[0]  * rstd;
    float ao = alpha_post[0] * rstd;

    float Z[16];
#pragma unroll
    for (int e = 0; e < 16; ++e)
        Z[e] = (beta_res[e] + ar * dp[e]) * (20.0f * LOG2E);

    float u[4] = {0.f, 0.f, 0.f, 0.f};
    float v[4] = {0.f, 0.f, 0.f, 0.f};
#pragma unroll 1
    for (int itn = 0; itn < 10; ++itn) {
#pragma unroll
        for (int i = 0; i < 4; ++i)
            u[i] = -lse4_2(Z[i*4+0] + v[0], Z[i*4+1] + v[1],
                           Z[i*4+2] + v[2], Z[i*4+3] + v[3]);
#pragma unroll
        for (int j = 0; j < 4; ++j)
            v[j] = -lse4_2(Z[0*4+j] + u[0], Z[1*4+j] + u[1],
                           Z[2*4+j] + u[2], Z[3*4+j] + u[3]);
    }

    float* hp = g_H + (size_t)tok * RROWS;
#pragma unroll
    for (int i = 0; i < 4; ++i)
#pragma unroll
        for (int j = 0; j < 4; ++j)
            hp[i*4+j] = ex2f(Z[i*4+j] + u[i] + v[j]);

    float p[4];
#pragma unroll
    for (int s = 0; s < 4; ++s)
        p[s] = (beta_pre[s] + ap * dp[16 + s]) * LOG2E;
    float m = fmaxf(fmaxf(p[0], p[1]), fmaxf(p[2], p[3]));
    float e0 = ex2f(p[0]-m), e1 = ex2f(p[1]-m);
    float e2 = ex2f(p[2]-m), e3 = ex2f(p[3]-m);
    float inv = 1.0f / (e0 + e1 + e2 + e3);
    hp[16] = e0*inv; hp[17] = e1*inv; hp[18] = e2*inv; hp[19] = e3*inv;

#pragma unroll
    for (int s = 0; s < 4; ++s) {
        float q = beta_post[s] + ao * dp[20 + s];
        hp[20 + s] = 2.0f / (1.0f + ex2f(-q * LOG2E));
    }
}

// ============================================================
// K3: out[i,d] = sum_j Hres[i][j] x[j,d] + Hpost[i] * sum_s Hpre[s] x[s,d]
// ============================================================
#define D4 1024
__global__ void __launch_bounds__(256)
mix_kernel(const float* __restrict__ x, float* __restrict__ out) {
    const int tok = blockIdx.x;
    const float* xr = x   + (size_t)tok * KDIM;
    float*       yr = out + (size_t)tok * KDIM;
    const float* hp = g_H + (size_t)tok * RROWS;

    float hres[16], hpre[4], hpost[4];
#pragma unroll
    for (int e = 0; e < 16; ++e) hres[e] = __ldg(hp + e);
#pragma unroll
    for (int s = 0; s < 4; ++s)  hpre[s]  = __ldg(hp + 16 + s);
#pragma unroll
    for (int s = 0; s < 4; ++s)  hpost[s] = __ldg(hp + 20 + s);

    const int col = threadIdx.x * 4;
    float4 xj[4];
#pragma unroll
    for (int j = 0; j < 4; ++j)
        xj[j] = __ldcs((const float4*)(xr + j * D4 + col));

    float4 bin;
    bin.x = hpre[0]*xj[0].x + hpre[1]*xj[1].x + hpre[2]*xj[2].x + hpre[3]*xj[3].x;
    bin.y = hpre[0]*xj[0].y + hpre[1]*xj[1].y + hpre[2]*xj[2].y + hpre[3]*xj[3].y;
    bin.z = hpre[0]*xj[0].z + hpre[1]*xj[1].z + hpre[2]*xj[2].z + hpre[3]*xj[3].z;
    bin.w = hpre[0]*xj[0].w + hpre[1]*xj[1].w + hpre[2]*xj[2].w + hpre[3]*xj[3].w;

#pragma unroll
    for (int i = 0; i < 4; ++i) {
        float4 o;
        o.x = hpost[i]*bin.x; o.y = hpost[i]*bin.y;
        o.z = hpost[i]*bin.z; o.w = hpost[i]*bin.w;
#pragma unroll
        for (int j = 0; j < 4; ++j) {
            float h = hres[i*4 + j];
            o.x += h * xj[j].x; o.y += h * xj[j].y;
            o.z += h * xj[j].z; o.w += h * xj[j].w;
        }
        __stcs((float4*)(yr + i * D4 + col), o);
    }
}

// ============================================================
// launch
// ============================================================
extern "C" void kernel_launch(void* const* d_in, const int* in_sizes, int n_in,
                              void* d_out, int out_size) {
    const float* residuals  = (const float*)d_in[0];
    const float* gamma      = (const float*)d_in[1];
    const float* w_res      = (const float*)d_in[2];
    const float* w_pre      = (const float*)d_in[3];
    const float* w_post     = (const float*)d_in[4];
    const float* beta_res   = (const float*)d_in[5];
    const float* beta_pre   = (const float*)d_in[6];
    const float* beta_post  = (const float*)d_in[7];
    const float* alpha_res  = (const float*)d_in[8];
    const float* alpha_pre  = (const float*)d_in[9];
    const float* alpha_post = (const float*)d_in[10];

    const int nt = in_sizes[0] / KDIM;   // B*T tokens (8192)

    static bool attr_set = false;
    if (!attr_set) {
        cudaFuncSetAttribute(dots_mma,
                             cudaFuncAttributeMaxDynamicSharedMemorySize,
                             SMEMD);
        attr_set = true;
    }

    prep_kernel<<<(RROWS * KDIM + 255) / 256, 256>>>(w_res, w_pre, w_post, gamma);
    dots_mma<<<nt / MTOK, 128, SMEMD>>>(residuals);
    heads_kernel<<<(nt + 127) / 128, 128>>>(beta_res, beta_pre, beta_post,
                                            alpha_res, alpha_pre, alpha_post, nt);
    mix_kernel<<<nt, 256>>>(residuals, (float*)d_out);
}

// round 11
// speedup vs baseline: 1.2039x; 1.0292x over previous
#include <cuda_runtime.h>
#include <math.h>
#include <stdint.h>

#define KDIM   4096
#define RROWS  24
#define MAXNT  8192

// ---- dots_mma geometry ----
#define MTOK   32                 // tokens per block
#define CKM    64                 // k per chunk
#define NCHM   (KDIM / CKM)       // 64 chunks
#define NBUFM  6                  // deep ring
#define LAHD   4                  // commit-ahead distance
#define XROW   68                 // padded floats per smem row
#define XSZ    (MTOK * XROW * 4)  // 8704 B
#define WSZ    (RROWS * XROW * 4) // 6528 B
#define STGB   (XSZ + WSZ)        // 15232 B
#define OFF_P  (NBUFM * STGB)             // partials [32*24] f32
#define OFF_Q  (OFF_P + MTOK * RROWS * 4) // ssq partials [32]
#define SMEMD  (OFF_Q + MTOK * 4)         // 94,592 B

// -------- scratch (no cudaMalloc allowed) --------
__device__ float g_wN  [RROWS * KDIM];   // gamma-folded, tf32-rounded weights
__device__ float g_dots[MAXNT * RROWS];
__device__ float g_ssq [MAXNT];
__device__ float g_H   [MAXNT * RROWS];

// ---------------- helpers ----------------
__device__ __forceinline__ void cpasync16(void* dst_smem, const void* src) {
    unsigned d = (unsigned)__cvta_generic_to_shared(dst_smem);
    asm volatile("cp.async.cg.shared.global [%0], [%1], 16;" :: "r"(d), "l"(src));
}
__device__ __forceinline__ float ex2f(float x) {
    float r; asm("ex2.approx.f32 %0, %1;" : "=f"(r) : "f"(x)); return r;
}
__device__ __forceinline__ float lg2f(float x) {
    float r; asm("lg2.approx.f32 %0, %1;" : "=f"(r) : "f"(x)); return r;
}
__device__ __forceinline__ uint32_t tf32r(float f) {
    uint32_t r; asm("cvt.rna.tf32.f32 %0, %1;" : "=r"(r) : "f"(f)); return r;
}
__device__ __forceinline__ void mma8(float* c, uint32_t a0, uint32_t a1,
                                     uint32_t a2, uint32_t a3,
                                     uint32_t b0, uint32_t b1) {
    asm volatile(
        "mma.sync.aligned.m16n8k8.row.col.f32.tf32.tf32.f32 "
        "{%0,%1,%2,%3}, {%4,%5,%6,%7}, {%8,%9}, {%0,%1,%2,%3};"
        : "+f"(c[0]), "+f"(c[1]), "+f"(c[2]), "+f"(c[3])
        : "r"(a0), "r"(a1), "r"(a2), "r"(a3), "r"(b0), "r"(b1));
}

// ============================================================
// K0: fold gamma into weights, round to tf32 once
// ============================================================
__global__ void prep_kernel(const float* __restrict__ w_res,
                            const float* __restrict__ w_pre,
                            const float* __restrict__ w_post,
                            const float* __restrict__ gamma) {
    int idx = blockIdx.x * blockDim.x + threadIdx.x;
    if (idx >= RROWS * KDIM) return;
    int r = idx >> 12;
    int k = idx & (KDIM - 1);
    float w;
    if (r < 16)      w = w_res [r * KDIM + k];
    else if (r < 20) w = w_pre [(r - 16) * KDIM + k];
    else             w = w_post[(r - 20) * KDIM + k];
    g_wN[idx] = __uint_as_float(tf32r(w * (1.0f + gamma[k])));
}

// ============================================================
// K1: dots via mma.sync m16n8k8 tf32 -- deep-pipeline version.
// Block = 32 tokens, 128 threads (4 warps), grid = 256 blocks.
// Warp = (m-tile = warp&1) x (K-half of each 64k chunk = warp>>1).
// 6-buffer cp.async ring, commit-ahead 4 (~800 cyc latency coverage),
// ONE barrier per chunk (safe: buffer reuse is >= 2 barrier
// generations after last read given NBUF=6, ahead=4).
// ============================================================
__global__ void __launch_bounds__(128, 2)
dots_mma(const float* __restrict__ x) {
    extern __shared__ __align__(16) char sm[];
    const int tid  = threadIdx.x;
    const int lane = tid & 31;
    const int warp = tid >> 5;            // 0..3
    const int mt   = warp & 1;            // m-tile
    const int grp  = warp >> 1;           // K-half of chunk
    const int g    = lane >> 2;           // 0..7
    const int tig  = lane & 3;            // 0..3
    const int tokb = blockIdx.x * MTOK;

    float* sP = (float*)(sm + OFF_P);
    float* sQ = (float*)(sm + OFF_Q);

#define STAGE(s) do {                                                          \
        if ((s) < NCHM) {                                                      \
            char* _b = sm + ((s) % NBUFM) * STGB;                              \
            const float* _xs = x + (size_t)tokb * KDIM + (s) * CKM;            \
            _Pragma("unroll")                                                  \
            for (int _j = 0; _j < 4; ++_j) {                                   \
                int _i = tid + 128 * _j;                                       \
                int _t = _i >> 4, _c = _i & 15;                                \
                cpasync16(_b + _t * (XROW * 4) + _c * 16,                      \
                          _xs + (size_t)_t * KDIM + _c * 4);                   \
            }                                                                  \
            _Pragma("unroll")                                                  \
            for (int _j = 0; _j < 3; ++_j) {                                   \
                int _i = tid + 128 * _j;                                       \
                int _t = _i >> 4, _c = _i & 15;                                \
                cpasync16(_b + XSZ + _t * (XROW * 4) + _c * 16,                \
                          g_wN + _t * KDIM + (s) * CKM + _c * 4);              \
            }                                                                  \
        }                                                                      \
        asm volatile("cp.async.commit_group;");                                \
    } while (0)

    float acc[3][4];
#pragma unroll
    for (int nt = 0; nt < 3; ++nt)
#pragma unroll
        for (int i = 0; i < 4; ++i) acc[nt][i] = 0.0f;
    float ssq0 = 0.0f, ssq1 = 0.0f;

    STAGE(0); STAGE(1); STAGE(2); STAGE(3);

    const int rowA0 = (mt * 16 + g) * XROW;
    const int rowA1 = rowA0 + 8 * XROW;

    for (int ch = 0; ch < NCHM; ++ch) {
        STAGE(ch + LAHD);
        asm volatile("cp.async.wait_group %0;" :: "n"(LAHD) : "memory");
        __syncthreads();

        const float* xb = (const float*)(sm + (ch % NBUFM) * STGB);
        const float* wb = xb + MTOK * XROW;

#pragma unroll
        for (int kt = 0; kt < 4; ++kt) {
            const int k0 = (grp * 4 + kt) * 8 + tig;
            float a0f = xb[rowA0 + k0];
            float a1f = xb[rowA1 + k0];
            float a2f = xb[rowA0 + k0 + 4];
            float a3f = xb[rowA1 + k0 + 4];
            ssq0 = fmaf(a0f, a0f, fmaf(a2f, a2f, ssq0));
            ssq1 = fmaf(a1f, a1f, fmaf(a3f, a3f, ssq1));
            uint32_t A0 = tf32r(a0f), A1 = tf32r(a1f);
            uint32_t A2 = tf32r(a2f), A3 = tf32r(a3f);
#pragma unroll
            for (int nt = 0; nt < 3; ++nt) {
                uint32_t B0 = __float_as_uint(wb[(nt * 8 + g) * XROW + k0]);
                uint32_t B1 = __float_as_uint(wb[(nt * 8 + g) * XROW + k0 + 4]);
                mma8(acc[nt], A0, A1, A2, A3, B0, B1);
            }
        }
        // no trailing barrier: buffer (ch%6) is only overwritten when
        // staging chunk ch+6 at iteration ch+2, i.e. >= 2 barrier
        // generations after every warp finished reading it.
    }

    // ---- quad-reduce ssq ----
    ssq0 += __shfl_down_sync(0xffffffffu, ssq0, 2, 4);
    ssq0 += __shfl_down_sync(0xffffffffu, ssq0, 1, 4);
    ssq1 += __shfl_down_sync(0xffffffffu, ssq1, 2, 4);
    ssq1 += __shfl_down_sync(0xffffffffu, ssq1, 1, 4);

    const int t0l = mt * 16 + g;
    const int t1l = t0l + 8;

    // ---- combine K-half partials through smem ----
    __syncthreads();
    if (grp == 1) {
#pragma unroll
        for (int nt = 0; nt < 3; ++nt) {
            int r = nt * 8 + 2 * tig;
            *(float2*)(sP + t0l * RROWS + r) = make_float2(acc[nt][0], acc[nt][1]);
            *(float2*)(sP + t1l * RROWS + r) = make_float2(acc[nt][2], acc[nt][3]);
        }
        if (tig == 0) { sQ[t0l] = ssq0; sQ[t1l] = ssq1; }
    }
    __syncthreads();
    if (grp == 0) {
        const int t0 = tokb + t0l, t1 = tokb + t1l;
#pragma unroll
        for (int nt = 0; nt < 3; ++nt) {
            int r = nt * 8 + 2 * tig;
            float2 p0 = *(const float2*)(sP + t0l * RROWS + r);
            float2 p1 = *(const float2*)(sP + t1l * RROWS + r);
            *(float2*)(g_dots + (size_t)t0 * RROWS + r) =
                make_float2(acc[nt][0] + p0.x, acc[nt][1] + p0.y);
            *(float2*)(g_dots + (size_t)t1 * RROWS + r) =
                make_float2(acc[nt][2] + p1.x, acc[nt][3] + p1.y);
        }
        if (tig == 0) {
            g_ssq[t0] = ssq0 + sQ[t0l];
            g_ssq[t1] = ssq1 + sQ[t1l];
        }
    }
#undef STAGE
}

// ============================================================
// K2: per-token heads (sinkhorn + softmax + sigmoid), base-2 MUFU
// ============================================================
#define LOG2E 1.4426950408889634f

__device__ __forceinline__ float lse4_2(float a, float b, float c, float d) {
    float m = fmaxf(fmaxf(a, b), fmaxf(c, d));
    float s = ex2f(a - m) + ex2f(b - m) + ex2f(c - m) + ex2f(d - m);
    return m + lg2f(s);
}

__global__ void heads_kernel(const float* __restrict__ beta_res,
                             const float* __restrict__ beta_pre,
                             const float* __restrict__ beta_post,
                             const float* __restrict__ alpha_res,
                             const float* __restrict__ alpha_pre,
                             const float* __restrict__ alpha_post,
                             int nt) {
    int tok = blockIdx.x * blockDim.x + threadIdx.x;
    if (tok >= nt) return;

    float rstd = 64.0f / fmaxf(sqrtf(g_ssq[tok]), 1e-12f);
    const float* dp = g_dots + (size_t)tok * RROWS;
    float ar = alpha_res[0]  * rstd;
    float ap = alpha_pre[0]  * rstd;
    float ao = alpha_post[0] * rstd;

    float Z[16];
#pragma unroll
    for (int e = 0; e < 16; ++e)
        Z[e] = (beta_res[e] + ar * dp[e]) * (20.0f * LOG2E);

    float u[4] = {0.f, 0.f, 0.f, 0.f};
    float v[4] = {0.f, 0.f, 0.f, 0.f};
#pragma unroll 1
    for (int itn = 0; itn < 10; ++itn) {
#pragma unroll
        for (int i = 0; i < 4; ++i)
            u[i] = -lse4_2(Z[i*4+0] + v[0], Z[i*4+1] + v[1],
                           Z[i*4+2] + v[2], Z[i*4+3] + v[3]);
#pragma unroll
        for (int j = 0; j < 4; ++j)
            v[j] = -lse4_2(Z[0*4+j] + u[0], Z[1*4+j] + u[1],
                           Z[2*4+j] + u[2], Z[3*4+j] + u[3]);
    }

    float* hp = g_H + (size_t)tok * RROWS;
#pragma unroll
    for (int i = 0; i < 4; ++i)
#pragma unroll
        for (int j = 0; j < 4; ++j)
            hp[i*4+j] = ex2f(Z[i*4+j] + u[i] + v[j]);

    float p[4];
#pragma unroll
    for (int s = 0; s < 4; ++s)
        p[s] = (beta_pre[s] + ap * dp[16 + s]) * LOG2E;
    float m = fmaxf(fmaxf(p[0], p[1]), fmaxf(p[2], p[3]));
    float e0 = ex2f(p[0]-m), e1 = ex2f(p[1]-m);
    float e2 = ex2f(p[2]-m), e3 = ex2f(p[3]-m);
    float inv = 1.0f / (e0 + e1 + e2 + e3);
    hp[16] = e0*inv; hp[17] = e1*inv; hp[18] = e2*inv; hp[19] = e3*inv;

#pragma unroll
    for (int s = 0; s < 4; ++s) {
        float q = beta_post[s] + ao * dp[20 + s];
        hp[20 + s] = 2.0f / (1.0f + ex2f(-q * LOG2E));
    }
}

// ============================================================
// K3: out[i,d] = sum_j Hres[i][j] x[j,d] + Hpost[i] * sum_s Hpre[s] x[s,d]
// ============================================================
#define D4 1024
__global__ void __launch_bounds__(256)
mix_kernel(const float* __restrict__ x, float* __restrict__ out) {
    const int tok = blockIdx.x;
    const float* xr = x   + (size_t)tok * KDIM;
    float*       yr = out + (size_t)tok * KDIM;
    const float* hp = g_H + (size_t)tok * RROWS;

    float hres[16], hpre[4], hpost[4];
#pragma unroll
    for (int e = 0; e < 16; ++e) hres[e] = __ldg(hp + e);
#pragma unroll
    for (int s = 0; s < 4; ++s)  hpre[s]  = __ldg(hp + 16 + s);
#pragma unroll
    for (int s = 0; s < 4; ++s)  hpost[s] = __ldg(hp + 20 + s);

    const int col = threadIdx.x * 4;
    float4 xj[4];
#pragma unroll
    for (int j = 0; j < 4; ++j)
        xj[j] = __ldcs((const float4*)(xr + j * D4 + col));

    float4 bin;
    bin.x = hpre[0]*xj[0].x + hpre[1]*xj[1].x + hpre[2]*xj[2].x + hpre[3]*xj[3].x;
    bin.y = hpre[0]*xj[0].y + hpre[1]*xj[1].y + hpre[2]*xj[2].y + hpre[3]*xj[3].y;
    bin.z = hpre[0]*xj[0].z + hpre[1]*xj[1].z + hpre[2]*xj[2].z + hpre[3]*xj[3].z;
    bin.w = hpre[0]*xj[0].w + hpre[1]*xj[1].w + hpre[2]*xj[2].w + hpre[3]*xj[3].w;

#pragma unroll
    for (int i = 0; i < 4; ++i) {
        float4 o;
        o.x = hpost[i]*bin.x; o.y = hpost[i]*bin.y;
        o.z = hpost[i]*bin.z; o.w = hpost[i]*bin.w;
#pragma unroll
        for (int j = 0; j < 4; ++j) {
            float h = hres[i*4 + j];
            o.x += h * xj[j].x; o.y += h * xj[j].y;
            o.z += h * xj[j].z; o.w += h * xj[j].w;
        }
        __stcs((float4*)(yr + i * D4 + col), o);
    }
}

// ============================================================
// launch
// ============================================================
extern "C" void kernel_launch(void* const* d_in, const int* in_sizes, int n_in,
                              void* d_out, int out_size) {
    const float* residuals  = (const float*)d_in[0];
    const float* gamma      = (const float*)d_in[1];
    const float* w_res      = (const float*)d_in[2];
    const float* w_pre      = (const float*)d_in[3];
    const float* w_post     = (const float*)d_in[4];
    const float* beta_res   = (const float*)d_in[5];
    const float* beta_pre   = (const float*)d_in[6];
    const float* beta_post  = (const float*)d_in[7];
    const float* alpha_res  = (const float*)d_in[8];
    const float* alpha_pre  = (const float*)d_in[9];
    const float* alpha_post = (const float*)d_in[10];

    const int nt = in_sizes[0] / KDIM;   // B*T tokens (8192)

    static bool attr_set = false;
    if (!attr_set) {
        cudaFuncSetAttribute(dots_mma,
                             cudaFuncAttributeMaxDynamicSharedMemorySize,
                             SMEMD);
        attr_set = true;
    }

    prep_kernel<<<(RROWS * KDIM + 255) / 256, 256>>>(w_res, w_pre, w_post, gamma);
    dots_mma<<<nt / MTOK, 128, SMEMD>>>(residuals);
    heads_kernel<<<(nt + 127) / 128, 128>>>(beta_res, beta_pre, beta_post,
                                            alpha_res, alpha_pre, alpha_post, nt);
    mix_kernel<<<nt, 256>>>(residuals, (float*)d_out);
}

// round 12
// speedup vs baseline: 1.2206x; 1.0138x over previous
#include <cuda_runtime.h>
#include <math.h>
#include <stdint.h>

#define KDIM   4096
#define RROWS  24
#define MAXNT  8192

// ---- dots_mma geometry (bf16 m16n8k16) ----
#define MTOK   32                 // tokens per block
#define CKM    64                 // k per chunk
#define NCHM   (KDIM / CKM)       // 64 chunks
#define NBUFM  6                  // ring depth
#define LAHD   4                  // commit-ahead distance
#define XROW   68                 // padded fp32 per x smem row
#define WROWW  36                 // padded u32 words per w smem row (32 data + 4 pad)
#define XSZ    (MTOK * XROW * 4)  // 8704 B
#define WSZ    (RROWS * WROWW * 4)// 3456 B
#define STGB   (XSZ + WSZ)        // 12160 B
#define OFF_P  (NBUFM * STGB)             // partials [32*24] f32
#define OFF_Q  (OFF_P + MTOK * RROWS * 4) // ssq partials [32]
#define SMEMD  (OFF_Q + MTOK * 4)         // 76,160 B

// -------- scratch (no cudaMalloc allowed) --------
__device__ uint32_t g_wB [RROWS * (KDIM / 2)];  // gamma-folded bf16x2 pairs
__device__ float g_dots[MAXNT * RROWS];
__device__ float g_ssq [MAXNT];
__device__ float g_H   [MAXNT * RROWS];

// ---------------- helpers ----------------
__device__ __forceinline__ void cpasync16(void* dst_smem, const void* src) {
    unsigned d = (unsigned)__cvta_generic_to_shared(dst_smem);
    asm volatile("cp.async.cg.shared.global [%0], [%1], 16;" :: "r"(d), "l"(src));
}
__device__ __forceinline__ float ex2f(float x) {
    float r; asm("ex2.approx.f32 %0, %1;" : "=f"(r) : "f"(x)); return r;
}
__device__ __forceinline__ float lg2f(float x) {
    float r; asm("lg2.approx.f32 %0, %1;" : "=f"(r) : "f"(x)); return r;
}
// pack float2 -> bf16x2 with v.x in low half (element k even)
__device__ __forceinline__ uint32_t bf2(float2 v) {
    uint32_t r;
    asm("cvt.rn.bf16x2.f32 %0, %1, %2;" : "=r"(r) : "f"(v.y), "f"(v.x));
    return r;
}
__device__ __forceinline__ uint32_t bf2s(float lo, float hi) {
    uint32_t r;
    asm("cvt.rn.bf16x2.f32 %0, %1, %2;" : "=r"(r) : "f"(hi), "f"(lo));
    return r;
}
__device__ __forceinline__ void mma16(float* c, uint32_t a0, uint32_t a1,
                                      uint32_t a2, uint32_t a3,
                                      uint32_t b0, uint32_t b1) {
    asm volatile(
        "mma.sync.aligned.m16n8k16.row.col.f32.bf16.bf16.f32 "
        "{%0,%1,%2,%3}, {%4,%5,%6,%7}, {%8,%9}, {%0,%1,%2,%3};"
        : "+f"(c[0]), "+f"(c[1]), "+f"(c[2]), "+f"(c[3])
        : "r"(a0), "r"(a1), "r"(a2), "r"(a3), "r"(b0), "r"(b1));
}

// ============================================================
// K0: fold gamma into weights, pack to bf16x2 pairs (k-major)
// ============================================================
__global__ void prep_kernel(const float* __restrict__ w_res,
                            const float* __restrict__ w_pre,
                            const float* __restrict__ w_post,
                            const float* __restrict__ gamma) {
    int idx = blockIdx.x * blockDim.x + threadIdx.x;
    if (idx >= RROWS * (KDIM / 2)) return;
    int r  = idx >> 11;            // / 2048
    int k  = (idx & 2047) * 2;
    const float* src;
    int rr = r;
    if (r < 16)      { src = w_res;  }
    else if (r < 20) { src = w_pre;  rr = r - 16; }
    else             { src = w_post; rr = r - 20; }
    float w0 = src[rr * KDIM + k]     * (1.0f + gamma[k]);
    float w1 = src[rr * KDIM + k + 1] * (1.0f + gamma[k + 1]);
    g_wB[idx] = bf2s(w0, w1);
}

// ============================================================
// K1: dots via mma.sync m16n8k16 bf16 (half the HMMA count of tf32).
// Block = 32 tokens, 128 threads (4 warps), grid = 256 blocks.
// Warp = (m-tile = warp&1) x (K-half of each 64k chunk = warp>>1).
// x staged fp32 (exact ssq from the same loads), w staged pre-packed
// bf16x2. 6-buffer cp.async ring, commit-ahead 4, one barrier/chunk.
// ============================================================
__global__ void __launch_bounds__(128, 2)
dots_mma(const float* __restrict__ x) {
    extern __shared__ __align__(16) char sm[];
    const int tid  = threadIdx.x;
    const int lane = tid & 31;
    const int warp = tid >> 5;            // 0..3
    const int mt   = warp & 1;            // m-tile
    const int grp  = warp >> 1;           // K-half of chunk
    const int g    = lane >> 2;           // 0..7
    const int tig  = lane & 3;            // 0..3
    const int tokb = blockIdx.x * MTOK;

    float* sP = (float*)(sm + OFF_P);
    float* sQ = (float*)(sm + OFF_Q);

#define STAGE(s) do {                                                          \
        if ((s) < NCHM) {                                                      \
            char* _b = sm + ((s) % NBUFM) * STGB;                              \
            const float* _xs = x + (size_t)tokb * KDIM + (s) * CKM;            \
            _Pragma("unroll")                                                  \
            for (int _j = 0; _j < 4; ++_j) {                                   \
                int _i = tid + 128 * _j;                                       \
                int _t = _i >> 4, _c = _i & 15;                                \
                cpasync16(_b + _t * (XROW * 4) + _c * 16,                      \
                          _xs + (size_t)_t * KDIM + _c * 4);                   \
            }                                                                  \
            _Pragma("unroll")                                                  \
            for (int _j = 0; _j < 2; ++_j) {                                   \
                int _i = tid + 128 * _j;                                       \
                if (_i < 192) {                                                \
                    int _r = _i >> 3, _c = _i & 7;                             \
                    cpasync16(_b + XSZ + _r * (WROWW * 4) + _c * 16,           \
                              g_wB + _r * (KDIM / 2) + (s) * 32 + _c * 4);     \
                }                                                              \
            }                                                                  \
        }                                                                      \
        asm volatile("cp.async.commit_group;");                                \
    } while (0)

    float acc[3][4];
#pragma unroll
    for (int nt = 0; nt < 3; ++nt)
#pragma unroll
        for (int i = 0; i < 4; ++i) acc[nt][i] = 0.0f;
    float ssq0 = 0.0f, ssq1 = 0.0f;

    STAGE(0); STAGE(1); STAGE(2); STAGE(3);

    const int rowA0 = (mt * 16 + g) * XROW;
    const int rowA1 = rowA0 + 8 * XROW;

    for (int ch = 0; ch < NCHM; ++ch) {
        STAGE(ch + LAHD);
        asm volatile("cp.async.wait_group %0;" :: "n"(LAHD) : "memory");
        __syncthreads();

        const float*    xb = (const float*)(sm + (ch % NBUFM) * STGB);
        const uint32_t* wb = (const uint32_t*)((const char*)xb + XSZ);

#pragma unroll
        for (int kt = 0; kt < 2; ++kt) {
            const int kb = grp * 32 + kt * 16 + 2 * tig;   // fp32 index
            float2 f0 = *(const float2*)(xb + rowA0 + kb);
            float2 f1 = *(const float2*)(xb + rowA1 + kb);
            float2 f2 = *(const float2*)(xb + rowA0 + kb + 8);
            float2 f3 = *(const float2*)(xb + rowA1 + kb + 8);
            ssq0 = fmaf(f0.x, f0.x, fmaf(f0.y, f0.y,
                   fmaf(f2.x, f2.x, fmaf(f2.y, f2.y, ssq0))));
            ssq1 = fmaf(f1.x, f1.x, fmaf(f1.y, f1.y,
                   fmaf(f3.x, f3.x, fmaf(f3.y, f3.y, ssq1))));
            uint32_t A0 = bf2(f0), A1 = bf2(f1), A2 = bf2(f2), A3 = bf2(f3);
            const int wbase = grp * 16 + kt * 8 + tig;     // u32 word in row
#pragma unroll
            for (int nt = 0; nt < 3; ++nt) {
                const uint32_t* wr = wb + (nt * 8 + g) * WROWW + wbase;
                uint32_t B0 = wr[0];
                uint32_t B1 = wr[4];
                mma16(acc[nt], A0, A1, A2, A3, B0, B1);
            }
        }
        // no trailing barrier: buffer (ch%6) is only rewritten when
        // staging chunk ch+6 at iteration ch+2 -- >= 2 barrier
        // generations after every warp finished reading it.
    }

    // ---- quad-reduce ssq ----
    ssq0 += __shfl_down_sync(0xffffffffu, ssq0, 2, 4);
    ssq0 += __shfl_down_sync(0xffffffffu, ssq0, 1, 4);
    ssq1 += __shfl_down_sync(0xffffffffu, ssq1, 2, 4);
    ssq1 += __shfl_down_sync(0xffffffffu, ssq1, 1, 4);

    const int t0l = mt * 16 + g;
    const int t1l = t0l + 8;

    // ---- combine K-half partials through smem ----
    __syncthreads();
    if (grp == 1) {
#pragma unroll
        for (int nt = 0; nt < 3; ++nt) {
            int r = nt * 8 + 2 * tig;
            *(float2*)(sP + t0l * RROWS + r) = make_float2(acc[nt][0], acc[nt][1]);
            *(float2*)(sP + t1l * RROWS + r) = make_float2(acc[nt][2], acc[nt][3]);
        }
        if (tig == 0) { sQ[t0l] = ssq0; sQ[t1l] = ssq1; }
    }
    __syncthreads();
    if (grp == 0) {
        const int t0 = tokb + t0l, t1 = tokb + t1l;
#pragma unroll
        for (int nt = 0; nt < 3; ++nt) {
            int r = nt * 8 + 2 * tig;
            float2 p0 = *(const float2*)(sP + t0l * RROWS + r);
            float2 p1 = *(const float2*)(sP + t1l * RROWS + r);
            *(float2*)(g_dots + (size_t)t0 * RROWS + r) =
                make_float2(acc[nt][0] + p0.x, acc[nt][1] + p0.y);
            *(float2*)(g_dots + (size_t)t1 * RROWS + r) =
                make_float2(acc[nt][2] + p1.x, acc[nt][3] + p1.y);
        }
        if (tig == 0) {
            g_ssq[t0] = ssq0 + sQ[t0l];
            g_ssq[t1] = ssq1 + sQ[t1l];
        }
    }
#undef STAGE
}

// ============================================================
// K2: per-token heads (sinkhorn + softmax + sigmoid), base-2 MUFU
// ============================================================
#define LOG2E 1.4426950408889634f

__device__ __forceinline__ float lse4_2(float a, float b, float c, float d) {
    float m = fmaxf(fmaxf(a, b), fmaxf(c, d));
    float s = ex2f(a - m) + ex2f(b - m) + ex2f(c - m) + ex2f(d - m);
    return m + lg2f(s);
}

__global__ void heads_kernel(const float* __restrict__ beta_res,
                             const float* __restrict__ beta_pre,
                             const float* __restrict__ beta_post,
                             const float* __restrict__ alpha_res,
                             const float* __restrict__ alpha_pre,
                             const float* __restrict__ alpha_post,
                             int nt) {
    int tok = blockIdx.x * blockDim.x + threadIdx.x;
    if (tok >= nt) return;

    float rstd = 64.0f / fmaxf(sqrtf(g_ssq[tok]), 1e-12f);
    const float* dp = g_dots + (size_t)tok * RROWS;
    float ar = alpha_res[0]  * rstd;
    float ap = alpha_pre[0]  * rstd;
    float ao = alpha_post[0] * rstd;

    float Z[16];
#pragma unroll
    for (int e = 0; e < 16; ++e)
        Z[e] = (beta_res[e] + ar * dp[e]) * (20.0f * LOG2E);

    float u[4] = {0.f, 0.f, 0.f, 0.f};
    float v[4] = {0.f, 0.f, 0.f, 0.f};
#pragma unroll 1
    for (int itn = 0; itn < 10; ++itn) {
#pragma unroll
        for (int i = 0; i < 4; ++i)
            u[i] = -lse4_2(Z[i*4+0] + v[0], Z[i*4+1] + v[1],
                           Z[i*4+2] + v[2], Z[i*4+3] + v[3]);
#pragma unroll
        for (int j = 0; j < 4; ++j)
            v[j] = -lse4_2(Z[0*4+j] + u[0], Z[1*4+j] + u[1],
                           Z[2*4+j] + u[2], Z[3*4+j] + u[3]);
    }

    float* hp = g_H + (size_t)tok * RROWS;
#pragma unroll
    for (int i = 0; i < 4; ++i)
#pragma unroll
        for (int j = 0; j < 4; ++j)
            hp[i*4+j] = ex2f(Z[i*4+j] + u[i] + v[j]);

    float p[4];
#pragma unroll
    for (int s = 0; s < 4; ++s)
        p[s] = (beta_pre[s] + ap * dp[16 + s]) * LOG2E;
    float m = fmaxf(fmaxf(p[0], p[1]), fmaxf(p[2], p[3]));
    float e0 = ex2f(p[0]-m), e1 = ex2f(p[1]-m);
    float e2 = ex2f(p[2]-m), e3 = ex2f(p[3]-m);
    float inv = 1.0f / (e0 + e1 + e2 + e3);
    hp[16] = e0*inv; hp[17] = e1*inv; hp[18] = e2*inv; hp[19] = e3*inv;

#pragma unroll
    for (int s = 0; s < 4; ++s) {
        float q = beta_post[s] + ao * dp[20 + s];
        hp[20 + s] = 2.0f / (1.0f + ex2f(-q * LOG2E));
    }
}

// ============================================================
// K3: out[i,d] = sum_j Hres[i][j] x[j,d] + Hpost[i] * sum_s Hpre[s] x[s,d]
// ============================================================
#define D4 1024
__global__ void __launch_bounds__(256)
mix_kernel(const float* __restrict__ x, float* __restrict__ out) {
    const int tok = blockIdx.x;
    const float* xr = x   + (size_t)tok * KDIM;
    float*       yr = out + (size_t)tok * KDIM;
    const float* hp = g_H + (size_t)tok * RROWS;

    float hres[16], hpre[4], hpost[4];
#pragma unroll
    for (int e = 0; e < 16; ++e) hres[e] = __ldg(hp + e);
#pragma unroll
    for (int s = 0; s < 4; ++s)  hpre[s]  = __ldg(hp + 16 + s);
#pragma unroll
    for (int s = 0; s < 4; ++s)  hpost[s] = __ldg(hp + 20 + s);

    const int col = threadIdx.x * 4;
    float4 xj[4];
#pragma unroll
    for (int j = 0; j < 4; ++j)
        xj[j] = __ldcs((const float4*)(xr + j * D4 + col));

    float4 bin;
    bin.x = hpre[0]*xj[0].x + hpre[1]*xj[1].x + hpre[2]*xj[2].x + hpre[3]*xj[3].x;
    bin.y = hpre[0]*xj[0].y + hpre[1]*xj[1].y + hpre[2]*xj[2].y + hpre[3]*xj[3].y;
    bin.z = hpre[0]*xj[0].z + hpre[1]*xj[1].z + hpre[2]*xj[2].z + hpre[3]*xj[3].z;
    bin.w = hpre[0]*xj[0].w + hpre[1]*xj[1].w + hpre[2]*xj[2].w + hpre[3]*xj[3].w;

#pragma unroll
    for (int i = 0; i < 4; ++i) {
        float4 o;
        o.x = hpost[i]*bin.x; o.y = hpost[i]*bin.y;
        o.z = hpost[i]*bin.z; o.w = hpost[i]*bin.w;
#pragma unroll
        for (int j = 0; j < 4; ++j) {
            float h = hres[i*4 + j];
            o.x += h * xj[j].x; o.y += h * xj[j].y;
            o.z += h * xj[j].z; o.w += h * xj[j].w;
        }
        __stcs((float4*)(yr + i * D4 + col), o);
    }
}

// ============================================================
// launch
// ============================================================
extern "C" void kernel_launch(void* const* d_in, const int* in_sizes, int n_in,
                              void* d_out, int out_size) {
    const float* residuals  = (const float*)d_in[0];
    const float* gamma      = (const float*)d_in[1];
    const float* w_res      = (const float*)d_in[2];
    const float* w_pre      = (const float*)d_in[3];
    const float* w_post     = (const float*)d_in[4];
    const float* beta_res   = (const float*)d_in[5];
    const float* beta_pre   = (const float*)d_in[6];
    const float* beta_post  = (const float*)d_in[7];
    const float* alpha_res  = (const float*)d_in[8];
    const float* alpha_pre  = (const float*)d_in[9];
    const float* alpha_post = (const float*)d_in[10];

    const int nt = in_sizes[0] / KDIM;   // B*T tokens (8192)

    static bool attr_set = false;
    if (!attr_set) {
        cudaFuncSetAttribute(dots_mma,
                             cudaFuncAttributeMaxDynamicSharedMemorySize,
                             SMEMD);
        attr_set = true;
    }

    prep_kernel<<<(RROWS * (KDIM / 2) + 255) / 256, 256>>>(w_res, w_pre,
                                                           w_post, gamma);
    dots_mma<<<nt / MTOK, 128, SMEMD>>>(residuals);
    heads_kernel<<<(nt + 127) / 128, 128>>>(beta_res, beta_pre, beta_post,
                                            alpha_res, alpha_pre, alpha_post, nt);
    mix_kernel<<<nt, 256>>>(residuals, (float*)d_out);
}